// round 3
// baseline (speedup 1.0000x reference)
#include <cuda_runtime.h>
#include <stdint.h>

#define D 768
#define H 64
#define E 7
#define BMAX 32768
#define TM 64      // rows per CTA tile
#define KC 32      // phase-1 K chunk
#define NC 128     // phase-2 N chunk

// ---- device scratch (no allocations allowed) ----
__device__ int d_counts[E];
__device__ int d_offsets[E + 1];
__device__ int d_cursor[E];
__device__ int d_perm[BMAX];
__device__ int d_is64;

// ---- dtype probe: int64 ids have every 8-byte word in [0,E); an int32
// buffer viewed as int64 combines random pairs and lands out of range
// with probability 1 - (1/7)^1024 ~ 1. Reads only first 8KB (safe for
// either dtype at B=32768). ----
__global__ void k_probe(const void* __restrict__ ids, int B) {
    __shared__ int bad;
    if (threadIdx.x == 0) bad = 0;
    __syncthreads();
    const long long* p = (const long long*)ids;
    int n = min(B / 2, 1024);   // B/2 int64 words always exist even if int32
    for (int i = threadIdx.x; i < n; i += blockDim.x) {
        long long v = p[i];
        if (v < 0 || v >= E) bad = 1;
    }
    __syncthreads();
    if (threadIdx.x == 0) d_is64 = bad ? 0 : 1;
}

__device__ __forceinline__ int load_id(const void* ids, int i, int is64) {
    if (is64) return (int)((const long long*)ids)[i];
    return ((const int*)ids)[i];
}

// ---- sorting scaffold ----
__global__ void k_zero() {
    if (threadIdx.x < E) d_counts[threadIdx.x] = 0;
}

__global__ void k_hist(const void* __restrict__ ids, int B) {
    __shared__ int sc[E];
    if (threadIdx.x < E) sc[threadIdx.x] = 0;
    __syncthreads();
    const int is64 = d_is64;
    for (int i = blockIdx.x * blockDim.x + threadIdx.x; i < B; i += gridDim.x * blockDim.x) {
        int e = load_id(ids, i, is64);
        if ((unsigned)e < E) atomicAdd(&sc[e], 1);
    }
    __syncthreads();
    if (threadIdx.x < E) atomicAdd(&d_counts[threadIdx.x], sc[threadIdx.x]);
}

__global__ void k_scan() {
    if (threadIdx.x == 0) {
        int acc = 0;
        for (int e = 0; e < E; e++) {
            d_offsets[e] = acc;
            d_cursor[e] = acc;
            acc += d_counts[e];
        }
        d_offsets[E] = acc;
    }
}

__global__ void k_scatter(const void* __restrict__ ids, int B) {
    const int is64 = d_is64;
    for (int i = blockIdx.x * blockDim.x + threadIdx.x; i < B; i += gridDim.x * blockDim.x) {
        int e = load_id(ids, i, is64);
        if ((unsigned)e < E) {
            int p = atomicAdd(&d_cursor[e], 1);
            d_perm[p] = i;
        }
    }
}

// ---- main fused adapter kernel ----
// Dynamic smem layout (floats):
//   Hs   : [64][68]            (4352)   persists across phases
//   union: phase1 {Xs[64][36] (2304), Ws1[32][68] (2176)}  |  phase2 Ws2[64][132] (8448)
//   b1s  : [64]
//   rowI : [64] ints
// total = (4352 + 8448 + 64 + 64) * 4 = 51712 bytes
__global__ void __launch_bounds__(256)
k_main(const float* __restrict__ x,
       const float* __restrict__ W1, const float* __restrict__ b1,
       const float* __restrict__ W2, const float* __restrict__ b2,
       float* __restrict__ out)
{
    const int e = blockIdx.y;
    const int seg0 = d_offsets[e];
    const int seg1 = d_offsets[e + 1];
    const int row0 = seg0 + blockIdx.x * TM;
    if (row0 >= seg1) return;
    const int nrows = min(TM, seg1 - row0);

    extern __shared__ float sm[];
    float* Hs  = sm;                 // 64*68
    float* P   = sm + 64 * 68;       // union base
    float* Xs  = P;                  // 64*36  (phase1)
    float* Ws1 = P + 64 * 36;        // 32*68  (phase1)
    float* Ws2 = P;                  // 64*132 (phase2)
    float* b1s = sm + 64 * 68 + 64 * 132;   // 64
    int*   rowI = (int*)(b1s + 64);         // 64

    const int tid = threadIdx.x;
    const int tx = tid & 15;
    const int ty = tid >> 4;

    if (tid < TM) {
        int r = (tid < nrows) ? tid : 0;
        rowI[tid] = d_perm[row0 + r];
    }
    if (tid < H) b1s[tid] = b1[(size_t)e * H + tid];
    __syncthreads();

    const float* W1e = W1 + (size_t)e * D * H;
    const float* W2e = W2 + (size_t)e * H * D;

    // ================= Phase 1: h = relu(x @ W1 + b1) =================
    float acc[4][4];
#pragma unroll
    for (int i = 0; i < 4; i++)
#pragma unroll
        for (int j = 0; j < 4; j++) acc[i][j] = 0.f;

    for (int kc = 0; kc < D; kc += KC) {
        // load X tile: thread -> row = tid>>2, 8 consecutive k
        {
            int r = tid >> 2, kq = tid & 3;
            const float* xr = x + (size_t)rowI[r] * D + kc + kq * 8;
            float4 v0 = *(const float4*)(xr);
            float4 v1 = *(const float4*)(xr + 4);
            *(float4*)&Xs[r * 36 + kq * 8]     = v0;
            *(float4*)&Xs[r * 36 + kq * 8 + 4] = v1;
        }
        // load W1 chunk [KC][H]: thread -> k = tid>>3, 8 consecutive cols
        {
            int k = tid >> 3, sg = tid & 7;
            const float* wr = W1e + (size_t)(kc + k) * H + sg * 8;
            float4 v0 = *(const float4*)(wr);
            float4 v1 = *(const float4*)(wr + 4);
            *(float4*)&Ws1[k * 68 + sg * 8]     = v0;
            *(float4*)&Ws1[k * 68 + sg * 8 + 4] = v1;
        }
        __syncthreads();

#pragma unroll
        for (int k = 0; k < KC; k += 4) {
            float a[4][4];   // [row][kk]
            float bm[4][4];  // [kk][col]
#pragma unroll
            for (int i = 0; i < 4; i++)
                *(float4*)a[i] = *(const float4*)&Xs[(4 * ty + i) * 36 + k];
#pragma unroll
            for (int kk = 0; kk < 4; kk++)
                *(float4*)bm[kk] = *(const float4*)&Ws1[(k + kk) * 68 + 4 * tx];
#pragma unroll
            for (int i = 0; i < 4; i++)
#pragma unroll
                for (int kk = 0; kk < 4; kk++)
#pragma unroll
                    for (int j = 0; j < 4; j++)
                        acc[i][j] += a[i][kk] * bm[kk][j];
        }
        __syncthreads();
    }

    // relu + bias, store transposed: Hs[col(k2)][row]
#pragma unroll
    for (int i = 0; i < 4; i++)
#pragma unroll
        for (int j = 0; j < 4; j++) {
            float v = acc[i][j] + b1s[4 * tx + j];
            Hs[(4 * tx + j) * 68 + (4 * ty + i)] = v > 0.f ? v : 0.f;
        }
    __syncthreads();

    // ================= Phase 2: out = x + h @ W2 + b2 =================
    for (int nc = 0; nc < D; nc += NC) {
        // load W2 chunk [H][NC]: thread -> k = tid>>2, 32 consecutive cols
        {
            int k = tid >> 2, sg = tid & 3;
            const float* wr = W2e + (size_t)k * D + nc + sg * 32;
            float* ds = &Ws2[k * 132 + sg * 32];
#pragma unroll
            for (int q = 0; q < 8; q++)
                ((float4*)ds)[q] = ((const float4*)wr)[q];
        }
        __syncthreads();

        float acc2[4][8];
#pragma unroll
        for (int i = 0; i < 4; i++)
#pragma unroll
            for (int j = 0; j < 8; j++) acc2[i][j] = 0.f;

#pragma unroll 8
        for (int k = 0; k < H; k++) {
            float av[4];
            float bv[8];
            *(float4*)av       = *(const float4*)&Hs[k * 68 + 4 * ty];
            *(float4*)(bv)     = *(const float4*)&Ws2[k * 132 + 8 * tx];
            *(float4*)(bv + 4) = *(const float4*)&Ws2[k * 132 + 8 * tx + 4];
#pragma unroll
            for (int i = 0; i < 4; i++)
#pragma unroll
                for (int j = 0; j < 8; j++)
                    acc2[i][j] += av[i] * bv[j];
        }

        // fused epilogue: out = x + y + b2
        const float* b2r = b2 + (size_t)e * D + nc + 8 * tx;
        float4 c0 = ((const float4*)b2r)[0];
        float4 c1 = ((const float4*)b2r)[1];
#pragma unroll
        for (int i = 0; i < 4; i++) {
            int r = 4 * ty + i;
            if (r < nrows) {
                int orig = rowI[r];
                const float* xr = x + (size_t)orig * D + nc + 8 * tx;
                float*       orow = out + (size_t)orig * D + nc + 8 * tx;
                float4 x0 = ((const float4*)xr)[0];
                float4 x1 = ((const float4*)xr)[1];
                float4 o0, o1;
                o0.x = x0.x + c0.x + acc2[i][0];
                o0.y = x0.y + c0.y + acc2[i][1];
                o0.z = x0.z + c0.z + acc2[i][2];
                o0.w = x0.w + c0.w + acc2[i][3];
                o1.x = x1.x + c1.x + acc2[i][4];
                o1.y = x1.y + c1.y + acc2[i][5];
                o1.z = x1.z + c1.z + acc2[i][6];
                o1.w = x1.w + c1.w + acc2[i][7];
                ((float4*)orow)[0] = o0;
                ((float4*)orow)[1] = o1;
            }
        }
        __syncthreads();  // protect Ws2 before next chunk load
    }
}

extern "C" void kernel_launch(void* const* d_in, const int* in_sizes, int n_in,
                              void* d_out, int out_size)
{
    const float* x   = (const float*)d_in[0];
    const void*  ids = d_in[1];
    const float* W1  = (const float*)d_in[2];
    const float* b1  = (const float*)d_in[3];
    const float* W2  = (const float*)d_in[4];
    const float* b2  = (const float*)d_in[5];
    float*       out = (float*)d_out;

    const int B = in_sizes[1];  // expert_ids element count

    k_probe<<<1, 256>>>(ids, B);
    k_zero<<<1, 32>>>();
    k_hist<<<128, 256>>>(ids, B);
    k_scan<<<1, 1>>>();
    k_scatter<<<128, 256>>>(ids, B);

    const size_t shmem = (size_t)(64 * 68 + 64 * 132 + 64 + 64) * 4;  // 51712 B
    cudaFuncSetAttribute(k_main, cudaFuncAttributeMaxDynamicSharedMemorySize, (int)shmem);

    dim3 grid((B + TM - 1) / TM, E);
    k_main<<<grid, 256, shmem>>>(x, W1, b1, W2, b2, out);
}

// round 6
// speedup vs baseline: 1.1797x; 1.1797x over previous
#include <cuda_runtime.h>
#include <stdint.h>

#define D 768
#define H 64
#define E 7
#define BMAX 32768

// ---------------- device scratch ----------------
__device__ int d_counts[E];
__device__ int d_offsets[E + 1];
__device__ int d_cursor[E];
__device__ int d_perm[BMAX];
__device__ int d_is64;

// ---------------- dtype probe / sort scaffold (verified round 3) ----------------
__global__ void k_probe(const void* __restrict__ ids, int B) {
    __shared__ int bad;
    if (threadIdx.x == 0) bad = 0;
    __syncthreads();
    const long long* p = (const long long*)ids;
    int n = min(B / 2, 1024);
    for (int i = threadIdx.x; i < n; i += blockDim.x) {
        long long v = p[i];
        if (v < 0 || v >= E) bad = 1;
    }
    __syncthreads();
    if (threadIdx.x == 0) d_is64 = bad ? 0 : 1;
}
__device__ __forceinline__ int load_id(const void* ids, int i, int is64) {
    return is64 ? (int)((const long long*)ids)[i] : ((const int*)ids)[i];
}
__global__ void k_zero() { if (threadIdx.x < E) d_counts[threadIdx.x] = 0; }
__global__ void k_hist(const void* __restrict__ ids, int B) {
    __shared__ int sc[E];
    if (threadIdx.x < E) sc[threadIdx.x] = 0;
    __syncthreads();
    const int is64 = d_is64;
    for (int i = blockIdx.x * blockDim.x + threadIdx.x; i < B; i += gridDim.x * blockDim.x) {
        int e = load_id(ids, i, is64);
        if ((unsigned)e < E) atomicAdd(&sc[e], 1);
    }
    __syncthreads();
    if (threadIdx.x < E) atomicAdd(&d_counts[threadIdx.x], sc[threadIdx.x]);
}
__global__ void k_scan() {
    if (threadIdx.x == 0) {
        int acc = 0;
        for (int e = 0; e < E; e++) { d_offsets[e] = acc; d_cursor[e] = acc; acc += d_counts[e]; }
        d_offsets[E] = acc;
    }
}
__global__ void k_scatter(const void* __restrict__ ids, int B) {
    const int is64 = d_is64;
    for (int i = blockIdx.x * blockDim.x + threadIdx.x; i < B; i += gridDim.x * blockDim.x) {
        int e = load_id(ids, i, is64);
        if ((unsigned)e < E) { int p = atomicAdd(&d_cursor[e], 1); d_perm[p] = i; }
    }
}

// ---------------- tf32 helpers ----------------
__device__ __forceinline__ float f2tf(float f) {
    uint32_t u;
    asm("cvt.rna.tf32.f32 %0, %1;" : "=r"(u) : "f"(f));
    return __uint_as_float(u);
}
__device__ __forceinline__ void mma_tf32(float* c, const uint32_t* a, uint32_t b0, uint32_t b1) {
    asm volatile(
        "mma.sync.aligned.m16n8k8.row.col.f32.tf32.tf32.f32 "
        "{%0,%1,%2,%3}, {%4,%5,%6,%7}, {%8,%9}, {%0,%1,%2,%3};\n"
        : "+f"(c[0]), "+f"(c[1]), "+f"(c[2]), "+f"(c[3])
        : "r"(a[0]), "r"(a[1]), "r"(a[2]), "r"(a[3]), "r"(b0), "r"(b1));
}

// ---------------- smem layout (float offsets) ----------------
#define HS_LD 68
#define XS_LD 36
#define W_LD 72
#define OFF_HS 0                         // 128*68 = 8704
#define OFF_X  8704                      // 128*36 = 4608
#define OFF_W1 13312                     // 32*72  = 2304 (end 15616)
#define OFF_W2 8704                      // 64*72  = 4608 (union with X/W1)
#define OFF_B1 15616                     // 64
#define OFF_B2 15680                     // 768
#define OFF_RI 16448                     // 128 ints
#define SMEM_FLOATS 16576                // 66304 bytes
#define SMEM_BYTES (SMEM_FLOATS * 4)

// ---------------- main tf32 mma.sync kernel ----------------
__global__ void __launch_bounds__(128)
k_main(const float* __restrict__ x,
       const float* __restrict__ W1, const float* __restrict__ b1,
       const float* __restrict__ W2, const float* __restrict__ b2,
       float* __restrict__ out)
{
    const int e = blockIdx.y;
    const int seg0 = d_offsets[e], seg1 = d_offsets[e + 1];
    const int row0 = seg0 + blockIdx.x * 128;
    if (row0 >= seg1) return;
    const int nrows = min(128, seg1 - row0);

    extern __shared__ float sm[];
    float* Hs  = sm + OFF_HS;
    float* Xs  = sm + OFF_X;
    float* W1s = sm + OFF_W1;
    float* W2s = sm + OFF_W2;
    float* b1s = sm + OFF_B1;
    float* b2s = sm + OFF_B2;
    int*   rowI = (int*)(sm + OFF_RI);

    const int tid = threadIdx.x;
    const int w = tid >> 5, lane = tid & 31;
    const int g = lane >> 2, tig = lane & 3;

    rowI[tid] = d_perm[(tid < nrows) ? (row0 + tid) : row0];
    if (tid < H) b1s[tid] = b1[e * H + tid];
#pragma unroll
    for (int i = tid; i < D; i += 128) b2s[i] = b2[e * D + i];
    __syncthreads();

    const float* xrow = x + (size_t)rowI[tid] * D;
    const float* W1e = W1 + (size_t)e * D * H;
    const float* W2e = W2 + (size_t)e * H * D;

    // ============ GEMM1: h = relu(X @ W1 + b1), tiles of K=32 ============
    float acc[2][8][4];
#pragma unroll
    for (int mt = 0; mt < 2; mt++)
#pragma unroll
        for (int nt = 0; nt < 8; nt++)
#pragma unroll
            for (int q = 0; q < 4; q++) acc[mt][nt][q] = 0.f;

#pragma unroll 1
    for (int kc = 0; kc < D; kc += 32) {
        {   // gather X chunk: thread = row, 32 floats, cvt->tf32
            const float4* src = (const float4*)(xrow + kc);
            float4* dst = (float4*)(Xs + tid * XS_LD);
#pragma unroll
            for (int q = 0; q < 8; q++) {
                float4 v = src[q];
                v.x = f2tf(v.x); v.y = f2tf(v.y); v.z = f2tf(v.z); v.w = f2tf(v.w);
                dst[q] = v;
            }
        }
        {   // W1 chunk [32][64] -> [32][W_LD]
            int k = tid >> 2, cq = tid & 3;
            const float4* src = (const float4*)(W1e + (size_t)(kc + k) * H + cq * 16);
            float4* dst = (float4*)(W1s + k * W_LD + cq * 16);
#pragma unroll
            for (int q = 0; q < 4; q++) {
                float4 v = src[q];
                v.x = f2tf(v.x); v.y = f2tf(v.y); v.z = f2tf(v.z); v.w = f2tf(v.w);
                dst[q] = v;
            }
        }
        __syncthreads();

#pragma unroll
        for (int ks = 0; ks < 4; ks++) {
            const int kb = ks * 8;
            uint32_t af[2][4];
#pragma unroll
            for (int mt = 0; mt < 2; mt++) {
                int r0 = w * 32 + mt * 16 + g;
                af[mt][0] = __float_as_uint(Xs[r0 * XS_LD + kb + tig]);
                af[mt][1] = __float_as_uint(Xs[(r0 + 8) * XS_LD + kb + tig]);
                af[mt][2] = __float_as_uint(Xs[r0 * XS_LD + kb + tig + 4]);
                af[mt][3] = __float_as_uint(Xs[(r0 + 8) * XS_LD + kb + tig + 4]);
            }
#pragma unroll
            for (int nt = 0; nt < 8; nt++) {
                uint32_t b0 = __float_as_uint(W1s[(kb + tig) * W_LD + nt * 8 + g]);
                uint32_t bb = __float_as_uint(W1s[(kb + tig + 4) * W_LD + nt * 8 + g]);
                mma_tf32(acc[0][nt], af[0], b0, bb);
                mma_tf32(acc[1][nt], af[1], b0, bb);
            }
        }
        __syncthreads();
    }

    // epilogue1: Hs = tf32(relu(acc + b1))
#pragma unroll
    for (int mt = 0; mt < 2; mt++) {
        int r0 = w * 32 + mt * 16 + g;
#pragma unroll
        for (int nt = 0; nt < 8; nt++) {
            int c = nt * 8 + tig * 2;
            float v0 = acc[mt][nt][0] + b1s[c];
            float v1 = acc[mt][nt][1] + b1s[c + 1];
            float v2 = acc[mt][nt][2] + b1s[c];
            float v3 = acc[mt][nt][3] + b1s[c + 1];
            Hs[r0 * HS_LD + c]           = f2tf(v0 > 0.f ? v0 : 0.f);
            Hs[r0 * HS_LD + c + 1]       = f2tf(v1 > 0.f ? v1 : 0.f);
            Hs[(r0 + 8) * HS_LD + c]     = f2tf(v2 > 0.f ? v2 : 0.f);
            Hs[(r0 + 8) * HS_LD + c + 1] = f2tf(v3 > 0.f ? v3 : 0.f);
        }
    }

    // per-thread row contexts for epilogue2 (rows w*32 + i*8 + g, i=0..3)
    bool val[4];
    const float* xp[4];
    float* op[4];
#pragma unroll
    for (int i = 0; i < 4; i++) {
        int r = w * 32 + i * 8 + g;
        val[i] = (r < nrows);
        int gr = rowI[r];
        xp[i] = x + (size_t)gr * D;
        op[i] = out + (size_t)gr * D;
    }

    // ============ GEMM2: out = x + h @ W2 + b2, 12 N-chunks of 64 ============
#pragma unroll 1
    for (int nc = 0; nc < 12; nc++) {
        __syncthreads();   // Hs writes done (first iter); W2s consumers done (later iters)
        {   // W2 tile [64][64] -> [64][W_LD]
            int k = tid >> 1, hf = tid & 1;
            const float4* src = (const float4*)(W2e + (size_t)k * D + nc * 64 + hf * 32);
            float4* dst = (float4*)(W2s + k * W_LD + hf * 32);
#pragma unroll
            for (int q = 0; q < 8; q++) {
                float4 v = src[q];
                v.x = f2tf(v.x); v.y = f2tf(v.y); v.z = f2tf(v.z); v.w = f2tf(v.w);
                dst[q] = v;
            }
        }
        __syncthreads();

        float acc2[2][8][4];
#pragma unroll
        for (int mt = 0; mt < 2; mt++)
#pragma unroll
            for (int nt = 0; nt < 8; nt++)
#pragma unroll
                for (int q = 0; q < 4; q++) acc2[mt][nt][q] = 0.f;

#pragma unroll
        for (int ks = 0; ks < 8; ks++) {
            const int kb = ks * 8;
            uint32_t af[2][4];
#pragma unroll
            for (int mt = 0; mt < 2; mt++) {
                int r0 = w * 32 + mt * 16 + g;
                af[mt][0] = __float_as_uint(Hs[r0 * HS_LD + kb + tig]);
                af[mt][1] = __float_as_uint(Hs[(r0 + 8) * HS_LD + kb + tig]);
                af[mt][2] = __float_as_uint(Hs[r0 * HS_LD + kb + tig + 4]);
                af[mt][3] = __float_as_uint(Hs[(r0 + 8) * HS_LD + kb + tig + 4]);
            }
#pragma unroll
            for (int nt = 0; nt < 8; nt++) {
                uint32_t b0 = __float_as_uint(W2s[(kb + tig) * W_LD + nt * 8 + g]);
                uint32_t bb = __float_as_uint(W2s[(kb + tig + 4) * W_LD + nt * 8 + g]);
                mma_tf32(acc2[0][nt], af[0], b0, bb);
                mma_tf32(acc2[1][nt], af[1], b0, bb);
            }
        }

        // fused epilogue: out = x + y + b2 (float2 per fragment half)
#pragma unroll
        for (int mt = 0; mt < 2; mt++) {
#pragma unroll
            for (int nt = 0; nt < 8; nt++) {
                int col = nc * 64 + nt * 8 + tig * 2;
                float2 bv = *(const float2*)(b2s + col);
                int i0 = mt * 2, i1 = mt * 2 + 1;
                if (val[i0]) {
                    float2 xv = *(const float2*)(xp[i0] + col);
                    float2 o;
                    o.x = xv.x + acc2[mt][nt][0] + bv.x;
                    o.y = xv.y + acc2[mt][nt][1] + bv.y;
                    *(float2*)(op[i0] + col) = o;
                }
                if (val[i1]) {
                    float2 xv = *(const float2*)(xp[i1] + col);
                    float2 o;
                    o.x = xv.x + acc2[mt][nt][2] + bv.x;
                    o.y = xv.y + acc2[mt][nt][3] + bv.y;
                    *(float2*)(op[i1] + col) = o;
                }
            }
        }
    }
}

extern "C" void kernel_launch(void* const* d_in, const int* in_sizes, int n_in,
                              void* d_out, int out_size)
{
    const float* x   = (const float*)d_in[0];
    const void*  ids = d_in[1];
    const float* W1  = (const float*)d_in[2];
    const float* b1  = (const float*)d_in[3];
    const float* W2  = (const float*)d_in[4];
    const float* b2  = (const float*)d_in[5];
    float*       out = (float*)d_out;

    const int B = in_sizes[1];

    k_probe<<<1, 256>>>(ids, B);
    k_zero<<<1, 32>>>();
    k_hist<<<128, 256>>>(ids, B);
    k_scan<<<1, 1>>>();
    k_scatter<<<128, 256>>>(ids, B);

    cudaFuncSetAttribute(k_main, cudaFuncAttributeMaxDynamicSharedMemorySize, SMEM_BYTES);
    dim3 grid((B + 127) / 128, E);
    k_main<<<grid, 128, SMEM_BYTES>>>(x, W1, b1, W2, b2, out);
}